// round 3
// baseline (speedup 1.0000x reference)
#include <cuda_runtime.h>
#include <math.h>

// Problem constants
#define BB 32
#define CC 273
#define TT 3000
#define OO 270
#define NF 32
#define DD 2048        // 2 * NF * NF
#define PH 1024        // NF * NF

// Scratch (allocations are forbidden; __device__ globals are the sanctioned path)
__device__ float g_emb[(size_t)BB * CC * DD];   // ~71.6 MB  [b][c][d]
__device__ float g_w[(size_t)BB * OO * CC];     // ~9.4 MB   scores -> weights in place [b][o][c]

// ---------------------------------------------------------------------------
// Stage 1: Fourier embedding.  emb[b,c, i*32+j]      = sin(2pi*(px*i + py*j))
//                              emb[b,c, 1024+i*32+j] = cos(...)
// Range-reduce arg to [0,1) before multiplying by 2pi so __sincosf is accurate
// regardless of fast-math; matches the fp32 reference to ~3e-5 absolute.
// ---------------------------------------------------------------------------
__global__ void emb_kernel(const float* __restrict__ layout) {
    int bc = blockIdx.x;                       // 0 .. B*C-1
    float px = (layout[bc * 2 + 0] + 0.1f) / 1.2f;
    float py = (layout[bc * 2 + 1] + 0.1f) / 1.2f;
    float* row = g_emb + (size_t)bc * DD;
    const float two_pi = 6.28318530717958647692f;
    for (int d = threadIdx.x; d < PH; d += blockDim.x) {
        int i = d >> 5;
        int j = d & 31;
        float arg = px * (float)i + py * (float)j;   // <= ~57
        arg -= floorf(arg);                           // [0,1)
        float s, c;
        __sincosf(two_pi * arg, &s, &c);
        row[d]      = s;
        row[PH + d] = c;
    }
}

// ---------------------------------------------------------------------------
// Stage 2: scores[b,o,c] = sum_d heads[o,d] * emb[b,c,d]
// Both operands K-major. 128x128 tile, BK=16, 256 threads, 8x8 per thread.
// ---------------------------------------------------------------------------
#define BM 128
#define BN 128
#define BK 16

__global__ __launch_bounds__(256) void scores_kernel(const float* __restrict__ heads) {
    __shared__ float As[BK][BM + 4];   // [k][o]
    __shared__ float Bs[BK][BN + 4];   // [k][c]
    int b  = blockIdx.z;
    int m0 = blockIdx.y * BM;          // o
    int n0 = blockIdx.x * BN;          // c
    int tid = threadIdx.x;
    int tm = tid >> 4;                 // 0..15
    int tn = tid & 15;                 // 0..15

    const float* __restrict__ embB = g_emb + (size_t)b * CC * DD;
    float acc[8][8] = {};

    for (int k0 = 0; k0 < DD; k0 += BK) {
        #pragma unroll
        for (int l = 0; l < 8; ++l) {
            int idx = tid + l * 256;          // 0..2047
            int r   = idx >> 4;               // tile row 0..127
            int kk  = idx & 15;               // 0..15
            int m = m0 + r;
            As[kk][r] = (m < OO) ? heads[(size_t)m * DD + k0 + kk] : 0.f;
            int n = n0 + r;
            Bs[kk][r] = (n < CC) ? embB[(size_t)n * DD + k0 + kk] : 0.f;
        }
        __syncthreads();
        #pragma unroll
        for (int kk = 0; kk < BK; ++kk) {
            float a[8], bb[8];
            #pragma unroll
            for (int i = 0; i < 8; ++i) a[i]  = As[kk][tm * 8 + i];
            #pragma unroll
            for (int j = 0; j < 8; ++j) bb[j] = Bs[kk][tn * 8 + j];
            #pragma unroll
            for (int i = 0; i < 8; ++i)
                #pragma unroll
                for (int j = 0; j < 8; ++j)
                    acc[i][j] = fmaf(a[i], bb[j], acc[i][j]);
        }
        __syncthreads();
    }

    #pragma unroll
    for (int i = 0; i < 8; ++i) {
        int o = m0 + tm * 8 + i;
        if (o >= OO) continue;
        #pragma unroll
        for (int j = 0; j < 8; ++j) {
            int c = n0 + tn * 8 + j;
            if (c < CC) g_w[((size_t)b * OO + o) * CC + c] = acc[i][j];
        }
    }
}

// ---------------------------------------------------------------------------
// Stage 3: softmax over c (273) for each of B*O rows, in place in g_w.
// ---------------------------------------------------------------------------
__global__ __launch_bounds__(128) void softmax_kernel() {
    int row = blockIdx.x;                          // b*O + o
    float* s = g_w + (size_t)row * CC;
    int tid  = threadIdx.x;
    __shared__ float sred[4];

    float m = -1e30f;
    for (int c = tid; c < CC; c += 128) m = fmaxf(m, s[c]);
    #pragma unroll
    for (int o = 16; o > 0; o >>= 1) m = fmaxf(m, __shfl_xor_sync(0xFFFFFFFFu, m, o));
    if ((tid & 31) == 0) sred[tid >> 5] = m;
    __syncthreads();
    m = fmaxf(fmaxf(sred[0], sred[1]), fmaxf(sred[2], sred[3]));
    __syncthreads();

    float sum = 0.f;
    for (int c = tid; c < CC; c += 128) {
        float e = __expf(s[c] - m);
        s[c] = e;
        sum += e;
    }
    #pragma unroll
    for (int o = 16; o > 0; o >>= 1) sum += __shfl_xor_sync(0xFFFFFFFFu, sum, o);
    if ((tid & 31) == 0) sred[tid >> 5] = sum;
    __syncthreads();
    sum = sred[0] + sred[1] + sred[2] + sred[3];

    float inv = 1.0f / sum;
    for (int c = tid; c < CC; c += 128) s[c] *= inv;
}

// ---------------------------------------------------------------------------
// Stage 4: out[b,o,t] = sum_c w[b,o,c] * brain[b,c,t]
// A = w (K-major), B = brain (N-major, fully coalesced). 128x128 tile, BK=16.
// ---------------------------------------------------------------------------
__global__ __launch_bounds__(256) void out_kernel(const float* __restrict__ brain,
                                                  float* __restrict__ out) {
    __shared__ float As[BK][BM + 4];   // [c][o]
    __shared__ float Bs[BK][BN];       // [c][t]
    int b  = blockIdx.z;
    int m0 = blockIdx.y * BM;          // o
    int n0 = blockIdx.x * BN;          // t
    int tid = threadIdx.x;
    int tm = tid >> 4;
    int tn = tid & 15;

    const float* __restrict__ wB = g_w   + (size_t)b * OO * CC;
    const float* __restrict__ xB = brain + (size_t)b * CC * TT;
    float acc[8][8] = {};

    for (int k0 = 0; k0 < CC; k0 += BK) {
        #pragma unroll
        for (int l = 0; l < 8; ++l) {
            int idx = tid + l * 256;
            int r   = idx >> 4;
            int kk  = idx & 15;
            int o = m0 + r, c = k0 + kk;
            As[kk][r] = (o < OO && c < CC) ? wB[(size_t)o * CC + c] : 0.f;
        }
        #pragma unroll
        for (int l = 0; l < 8; ++l) {
            int idx = tid + l * 256;
            int kk  = idx >> 7;                 // 0..15
            int col = idx & 127;                // 0..127
            int c = k0 + kk, t = n0 + col;
            Bs[kk][col] = (c < CC && t < TT) ? xB[(size_t)c * TT + t] : 0.f;
        }
        __syncthreads();
        #pragma unroll
        for (int kk = 0; kk < BK; ++kk) {
            float a[8], bb[8];
            #pragma unroll
            for (int i = 0; i < 8; ++i) a[i]  = As[kk][tm * 8 + i];
            #pragma unroll
            for (int j = 0; j < 8; ++j) bb[j] = Bs[kk][tn * 8 + j];
            #pragma unroll
            for (int i = 0; i < 8; ++i)
                #pragma unroll
                for (int j = 0; j < 8; ++j)
                    acc[i][j] = fmaf(a[i], bb[j], acc[i][j]);
        }
        __syncthreads();
    }

    #pragma unroll
    for (int i = 0; i < 8; ++i) {
        int o = m0 + tm * 8 + i;
        if (o >= OO) continue;
        #pragma unroll
        for (int j = 0; j < 8; ++j) {
            int t = n0 + tn * 8 + j;
            if (t < TT) out[((size_t)b * OO + o) * TT + t] = acc[i][j];
        }
    }
}

// ---------------------------------------------------------------------------
// Launch: emb -> scores -> softmax -> out (default stream, graph-capturable)
// ---------------------------------------------------------------------------
extern "C" void kernel_launch(void* const* d_in, const int* in_sizes, int n_in,
                              void* d_out, int out_size) {
    const float* brain  = (const float*)d_in[0];   // [32, 273, 3000]
    const float* layout = (const float*)d_in[1];   // [32, 273, 2]
    const float* heads  = (const float*)d_in[2];   // [270, 2048]
    float* out = (float*)d_out;                    // [32, 270, 3000]

    emb_kernel<<<BB * CC, 256>>>(layout);

    dim3 gs((CC + BN - 1) / BN, (OO + BM - 1) / BM, BB);   // (3, 3, 32)
    scores_kernel<<<gs, 256>>>(heads);

    softmax_kernel<<<BB * OO, 128>>>();

    dim3 go((TT + BN - 1) / BN, (OO + BM - 1) / BM, BB);   // (24, 3, 32)
    out_kernel<<<go, 256>>>(brain, out);
}

// round 4
// speedup vs baseline: 2.2389x; 2.2389x over previous
#include <cuda_runtime.h>
#include <mma.h>
#include <math.h>

using namespace nvcuda;

// Problem constants
#define BB 32
#define CC 273
#define CP 288          // padded channel dim (multiple of 16) for stage-4 K
#define TT 3000
#define OO 270
#define DD 2048         // 2 * 32 * 32
#define PH 1024

#define BKP 20          // smem K-pitch (16 + pad, multiple of 4 floats)

// Scratch (__device__ globals; allocations forbidden)
__device__ float g_emb[(size_t)BB * CC * DD];   // ~71.6 MB  [b][c][d]
__device__ float g_w[(size_t)BB * OO * CP];     // ~10 MB    [b][o][c], c padded to 288

// ---------------------------------------------------------------------------
// Stage 1: Fourier embedding, separable form.
//   sin(2pi(px*i + py*j)) = sx[i]*cy[j] + cx[i]*sy[j]
//   cos(2pi(px*i + py*j)) = cx[i]*cy[j] - sx[i]*sy[j]
// 64 sincos per (b,c) instead of 1024 -> HBM-write bound (~12us).
// ---------------------------------------------------------------------------
__global__ __launch_bounds__(256) void emb_kernel(const float* __restrict__ layout) {
    __shared__ float sx[32], cx[32], sy[32], cy[32];
    int bc = blockIdx.x;
    const float two_pi = 6.28318530717958647692f;
    if (threadIdx.x < 64) {
        int i = threadIdx.x & 31;
        float p = (threadIdx.x < 32)
                ? (layout[bc * 2 + 0] + 0.1f) / 1.2f
                : (layout[bc * 2 + 1] + 0.1f) / 1.2f;
        float a = p * (float)i;
        a -= floorf(a);                    // [0,1) so __sincosf is accurate
        float s, c;
        __sincosf(two_pi * a, &s, &c);
        if (threadIdx.x < 32) { sx[i] = s; cx[i] = c; }
        else                  { sy[i] = s; cy[i] = c; }
    }
    __syncthreads();
    float* row = g_emb + (size_t)bc * DD;
    for (int d = threadIdx.x; d < PH; d += 256) {
        int i = d >> 5, j = d & 31;
        float a = sx[i], b = cx[i], c = sy[j], e = cy[j];
        row[d]      = a * e + b * c;       // sin
        row[PH + d] = b * e - a * c;       // cos
    }
}

// ---------------------------------------------------------------------------
// Stage 2: scores[b,o,c] = sum_d heads[o,d] * emb[b,c,d]   (tf32 tensor core)
// Block tile 96x96, BK=16, 6 warps (3x2), warp tile 32x48 (2x3 wmma frags).
// Both operands K-major in gmem; B loaded as col-major fragments.
// Output goes to g_w with row stride CP=288 (pad cols get zeros).
// ---------------------------------------------------------------------------
__global__ __launch_bounds__(192) void scores_kernel(const float* __restrict__ heads) {
    __shared__ float As[96][BKP];            // [o][k]
    __shared__ float Bs[96][BKP];            // [c][k]
    __shared__ float patch[6][16][BKP];      // per-warp edge staging

    int b  = blockIdx.z;
    int m0 = blockIdx.y * 96;                // o
    int n0 = blockIdx.x * 96;                // c
    int tid = threadIdx.x, warp = tid >> 5, lane = tid & 31;
    int wm = warp >> 1, wn = warp & 1;

    const float* __restrict__ embB = g_emb + (size_t)b * CC * DD;

    wmma::fragment<wmma::accumulator, 16, 16, 8, float> acc[2][3];
    #pragma unroll
    for (int i = 0; i < 2; ++i)
        #pragma unroll
        for (int j = 0; j < 3; ++j) wmma::fill_fragment(acc[i][j], 0.0f);

    for (int k0 = 0; k0 < DD; k0 += 16) {
        #pragma unroll
        for (int l = 0; l < 2; ++l) {
            int idx = tid + l * 192;         // 0..383 (float4 slots)
            int row = idx >> 2, q = idx & 3;
            float4 va = make_float4(0.f, 0.f, 0.f, 0.f), vb = va;
            int o = m0 + row;
            if (o < OO) va = *(const float4*)&heads[(size_t)o * DD + k0 + q * 4];
            int c = n0 + row;
            if (c < CC) vb = *(const float4*)&embB[(size_t)c * DD + k0 + q * 4];
            *(float4*)&As[row][q * 4] = va;
            *(float4*)&Bs[row][q * 4] = vb;
        }
        __syncthreads();
        #pragma unroll
        for (int kk = 0; kk < 16; kk += 8) {
            wmma::fragment<wmma::matrix_a, 16, 16, 8, wmma::precision::tf32, wmma::row_major> a[2];
            wmma::fragment<wmma::matrix_b, 16, 16, 8, wmma::precision::tf32, wmma::col_major> bf[3];
            #pragma unroll
            for (int i = 0; i < 2; ++i) {
                wmma::load_matrix_sync(a[i], &As[wm * 32 + i * 16][kk], BKP);
                #pragma unroll
                for (int e = 0; e < a[i].num_elements; ++e)
                    a[i].x[e] = wmma::__float_to_tf32(a[i].x[e]);
            }
            #pragma unroll
            for (int j = 0; j < 3; ++j) {
                wmma::load_matrix_sync(bf[j], &Bs[wn * 48 + j * 16][kk], BKP);
                #pragma unroll
                for (int e = 0; e < bf[j].num_elements; ++e)
                    bf[j].x[e] = wmma::__float_to_tf32(bf[j].x[e]);
            }
            #pragma unroll
            for (int i = 0; i < 2; ++i)
                #pragma unroll
                for (int j = 0; j < 3; ++j)
                    wmma::mma_sync(acc[i][j], a[i], bf[j], acc[i][j]);
        }
        __syncthreads();
    }

    float* wrow = g_w + (size_t)b * OO * CP;
    #pragma unroll
    for (int i = 0; i < 2; ++i) {
        #pragma unroll
        for (int j = 0; j < 3; ++j) {
            int r0 = m0 + wm * 32 + i * 16;
            int c0 = n0 + wn * 48 + j * 16;      // always < CP
            if (r0 + 16 <= OO) {
                wmma::store_matrix_sync(&wrow[(size_t)r0 * CP + c0], acc[i][j],
                                        CP, wmma::mem_row_major);
            } else {
                wmma::store_matrix_sync(&patch[warp][0][0], acc[i][j],
                                        BKP, wmma::mem_row_major);
                __syncwarp();
                for (int e = lane; e < 256; e += 32) {
                    int r = e >> 4, cc2 = e & 15;
                    if (r0 + r < OO)
                        wrow[(size_t)(r0 + r) * CP + c0 + cc2] = patch[warp][r][cc2];
                }
                __syncwarp();
            }
        }
    }
}

// ---------------------------------------------------------------------------
// Stage 3: softmax over c (first 273 of 288) per (b,o) row; zero the pad.
// ---------------------------------------------------------------------------
__global__ __launch_bounds__(128) void softmax_kernel() {
    int row = blockIdx.x;
    float* s = g_w + (size_t)row * CP;
    int tid = threadIdx.x;
    __shared__ float sred[4];

    float m = -1e30f;
    for (int c = tid; c < CC; c += 128) m = fmaxf(m, s[c]);
    #pragma unroll
    for (int o = 16; o > 0; o >>= 1) m = fmaxf(m, __shfl_xor_sync(0xFFFFFFFFu, m, o));
    if ((tid & 31) == 0) sred[tid >> 5] = m;
    __syncthreads();
    m = fmaxf(fmaxf(sred[0], sred[1]), fmaxf(sred[2], sred[3]));
    __syncthreads();

    float sum = 0.f;
    for (int c = tid; c < CC; c += 128) {
        float e = __expf(s[c] - m);
        s[c] = e;
        sum += e;
    }
    #pragma unroll
    for (int o = 16; o > 0; o >>= 1) sum += __shfl_xor_sync(0xFFFFFFFFu, sum, o);
    if ((tid & 31) == 0) sred[tid >> 5] = sum;
    __syncthreads();
    sum = sred[0] + sred[1] + sred[2] + sred[3];

    float inv = 1.0f / sum;
    for (int c = tid; c < CP; c += 128) {
        if (c < CC) s[c] *= inv;
        else        s[c] = 0.f;           // pad cols must be exact zero for stage 4
    }
}

// ---------------------------------------------------------------------------
// Stage 4: out[b,o,t] = sum_c w[b,o,c] * brain[b,c,t]   (tf32 tensor core)
// Block tile 96x128, BK=16, K=CP=288 (w pad is zero so no K guard on A).
// 6 warps (3x2), warp tile 32x64 (2x4 wmma frags). B fragments row-major.
// ---------------------------------------------------------------------------
#define OBN  128
#define OBNP 132

__global__ __launch_bounds__(192) void out_kernel(const float* __restrict__ brain,
                                                  float* __restrict__ out) {
    __shared__ float As[96][BKP];            // [o][c]
    __shared__ float Bs[16][OBNP];           // [c][t]
    __shared__ float patch[6][16][BKP];

    int b  = blockIdx.z;
    int m0 = blockIdx.y * 96;                // o
    int n0 = blockIdx.x * OBN;               // t
    int tid = threadIdx.x, warp = tid >> 5, lane = tid & 31;
    int wm = warp >> 1, wn = warp & 1;

    const float* __restrict__ wB = g_w   + (size_t)b * OO * CP;
    const float* __restrict__ xB = brain + (size_t)b * CC * TT;

    wmma::fragment<wmma::accumulator, 16, 16, 8, float> acc[2][4];
    #pragma unroll
    for (int i = 0; i < 2; ++i)
        #pragma unroll
        for (int j = 0; j < 4; ++j) wmma::fill_fragment(acc[i][j], 0.0f);

    for (int k0 = 0; k0 < CP; k0 += 16) {
        // A tile: 96x16 = 384 float4 slots
        #pragma unroll
        for (int l = 0; l < 2; ++l) {
            int idx = tid + l * 192;
            int row = idx >> 2, q = idx & 3;
            int o = m0 + row;
            float4 v = make_float4(0.f, 0.f, 0.f, 0.f);
            if (o < OO) v = *(const float4*)&wB[(size_t)o * CP + k0 + q * 4];
            *(float4*)&As[row][q * 4] = v;
        }
        // B tile: 16x128 = 512 float4 slots
        #pragma unroll
        for (int l = 0; l < 3; ++l) {
            int idx = tid + l * 192;
            if (idx < 512) {
                int row = idx >> 5, col = (idx & 31) * 4;
                int c = k0 + row, t = n0 + col;
                float4 v = make_float4(0.f, 0.f, 0.f, 0.f);
                if (c < CC && t < TT) v = *(const float4*)&xB[(size_t)c * TT + t];
                *(float4*)&Bs[row][col] = v;
            }
        }
        __syncthreads();
        #pragma unroll
        for (int kk = 0; kk < 16; kk += 8) {
            wmma::fragment<wmma::matrix_a, 16, 16, 8, wmma::precision::tf32, wmma::row_major> a[2];
            wmma::fragment<wmma::matrix_b, 16, 16, 8, wmma::precision::tf32, wmma::row_major> bf[4];
            #pragma unroll
            for (int i = 0; i < 2; ++i) {
                wmma::load_matrix_sync(a[i], &As[wm * 32 + i * 16][kk], BKP);
                #pragma unroll
                for (int e = 0; e < a[i].num_elements; ++e)
                    a[i].x[e] = wmma::__float_to_tf32(a[i].x[e]);
            }
            #pragma unroll
            for (int j = 0; j < 4; ++j) {
                wmma::load_matrix_sync(bf[j], &Bs[kk][wn * 64 + j * 16], OBNP);
                #pragma unroll
                for (int e = 0; e < bf[j].num_elements; ++e)
                    bf[j].x[e] = wmma::__float_to_tf32(bf[j].x[e]);
            }
            #pragma unroll
            for (int i = 0; i < 2; ++i)
                #pragma unroll
                for (int j = 0; j < 4; ++j)
                    wmma::mma_sync(acc[i][j], a[i], bf[j], acc[i][j]);
        }
        __syncthreads();
    }

    #pragma unroll
    for (int i = 0; i < 2; ++i) {
        #pragma unroll
        for (int j = 0; j < 4; ++j) {
            int r0 = m0 + wm * 32 + i * 16;
            int t0 = n0 + wn * 64 + j * 16;
            if (r0 + 16 <= OO && t0 + 16 <= TT) {
                wmma::store_matrix_sync(&out[((size_t)b * OO + r0) * TT + t0],
                                        acc[i][j], TT, wmma::mem_row_major);
            } else {
                wmma::store_matrix_sync(&patch[warp][0][0], acc[i][j],
                                        BKP, wmma::mem_row_major);
                __syncwarp();
                for (int e = lane; e < 256; e += 32) {
                    int r = e >> 4, cc2 = e & 15;
                    int o = r0 + r, t = t0 + cc2;
                    if (o < OO && t < TT)
                        out[((size_t)b * OO + o) * TT + t] = patch[warp][r][cc2];
                }
                __syncwarp();
            }
        }
    }
}

// ---------------------------------------------------------------------------
// Launch: emb -> scores -> softmax -> out (default stream, graph-capturable)
// ---------------------------------------------------------------------------
extern "C" void kernel_launch(void* const* d_in, const int* in_sizes, int n_in,
                              void* d_out, int out_size) {
    const float* brain  = (const float*)d_in[0];   // [32, 273, 3000]
    const float* layout = (const float*)d_in[1];   // [32, 273, 2]
    const float* heads  = (const float*)d_in[2];   // [270, 2048]
    float* out = (float*)d_out;                    // [32, 270, 3000]

    emb_kernel<<<BB * CC, 256>>>(layout);

    dim3 gs((CP + 95) / 96, (OO + 95) / 96, BB);          // (3, 3, 32)
    scores_kernel<<<gs, 192>>>(heads);

    softmax_kernel<<<BB * OO, 128>>>();

    dim3 go((TT + OBN - 1) / OBN, (OO + 95) / 96, BB);    // (24, 3, 32)
    out_kernel<<<go, 192>>>(brain, out);
}

// round 7
// speedup vs baseline: 2.5788x; 1.1518x over previous
#include <cuda_runtime.h>
#include <mma.h>
#include <math.h>
#include <cstdint>

using namespace nvcuda;

// Problem constants
#define BB 32
#define CC 273
#define CP 288          // padded channel dim
#define TT 3000
#define OO 270
#define DD 2048
#define PH 1024

// Scratch
__device__ float g_emb[(size_t)BB * CC * DD];   // [b][c][d]
__device__ float g_w[(size_t)BB * OO * CP];     // [b][o][c] padded

// ---------------------------------------------------------------------------
// cp.async helpers (16B, L1-bypass, zero-fill when pred==false)
// ---------------------------------------------------------------------------
__device__ __forceinline__ void cp_async16(float* smem, const float* gmem, bool pred) {
    unsigned int s = (unsigned int)__cvta_generic_to_shared(smem);
    int sz = pred ? 16 : 0;
    asm volatile("cp.async.cg.shared.global [%0], [%1], 16, %2;\n"
                 :: "r"(s), "l"(gmem), "r"(sz));
}
__device__ __forceinline__ void cp_commit() {
    asm volatile("cp.async.commit_group;\n" ::: "memory");
}
template <int N>
__device__ __forceinline__ void cp_wait() {
    asm volatile("cp.async.wait_group %0;\n" :: "n"(N) : "memory");
}

// ---------------------------------------------------------------------------
// Stage 1: separable Fourier embedding (HBM-write bound, ~12us)
// ---------------------------------------------------------------------------
__global__ __launch_bounds__(256) void emb_kernel(const float* __restrict__ layout) {
    __shared__ float sx[32], cx[32], sy[32], cy[32];
    int bc = blockIdx.x;
    const float two_pi = 6.28318530717958647692f;
    if (threadIdx.x < 64) {
        int i = threadIdx.x & 31;
        float p = (threadIdx.x < 32)
                ? (layout[bc * 2 + 0] + 0.1f) / 1.2f
                : (layout[bc * 2 + 1] + 0.1f) / 1.2f;
        float a = p * (float)i;
        a -= floorf(a);
        float s, c;
        __sincosf(two_pi * a, &s, &c);
        if (threadIdx.x < 32) { sx[i] = s; cx[i] = c; }
        else                  { sy[i] = s; cy[i] = c; }
    }
    __syncthreads();
    float* row = g_emb + (size_t)bc * DD;
    for (int d = threadIdx.x; d < PH; d += 256) {
        int i = d >> 5, j = d & 31;
        float a = sx[i], b = cx[i], c = sy[j], e = cy[j];
        row[d]      = a * e + b * c;       // sin
        row[PH + d] = b * e - a * c;       // cos
    }
}

// ---------------------------------------------------------------------------
// Stage 2: scores[b,o,c] = heads[o,:] . emb[b,c,:]   (tf32, 2-stage cp.async)
// Block 96x96, BK=16, 6 warps (3x2), warp tile 32x48 (2x3 frags).
// ---------------------------------------------------------------------------
#define SKP 20          // smem K pitch (floats); 80B = 5x16B, cp.async-aligned

__global__ __launch_bounds__(192) void scores_kernel(const float* __restrict__ heads) {
    __shared__ float sm[4 * 96 * SKP];     // As[2][96][20] | Bs[2][96][20] = 30.7KB
    float* Asb = sm;                       // + s*1920
    float* Bsb = sm + 2 * 96 * SKP;        // + s*1920

    int b  = blockIdx.z;
    int m0 = blockIdx.y * 96;
    int n0 = blockIdx.x * 96;
    int tid = threadIdx.x, warp = tid >> 5, lane = tid & 31;
    int wm = warp >> 1, wn = warp & 1;

    const float* __restrict__ embB = g_emb + (size_t)b * CC * DD;

    wmma::fragment<wmma::accumulator, 16, 16, 8, float> acc[2][3];
    #pragma unroll
    for (int i = 0; i < 2; ++i)
        #pragma unroll
        for (int j = 0; j < 3; ++j) wmma::fill_fragment(acc[i][j], 0.0f);

    const int NK = DD / 16;   // 128

    // ---- load one K-tile into stage s ----
    auto load_tile = [&](int s, int k0) {
        float* As = Asb + s * 96 * SKP;
        float* Bs = Bsb + s * 96 * SKP;
        #pragma unroll
        for (int l = 0; l < 2; ++l) {
            int idx = tid + l * 192;          // 0..383 float4 slots
            int row = idx >> 2, q = idx & 3;
            int o = m0 + row;
            cp_async16(&As[row * SKP + q * 4], &heads[(size_t)o * DD + k0 + q * 4], o < OO);
            int c = n0 + row;
            cp_async16(&Bs[row * SKP + q * 4], &embB[(size_t)c * DD + k0 + q * 4], c < CC);
        }
        cp_commit();
    };

    load_tile(0, 0);
    for (int ks = 0; ks < NK; ++ks) {
        if (ks + 1 < NK) { load_tile((ks + 1) & 1, (ks + 1) * 16); cp_wait<1>(); }
        else             { cp_wait<0>(); }
        __syncthreads();

        const float* As = Asb + (ks & 1) * 96 * SKP;
        const float* Bs = Bsb + (ks & 1) * 96 * SKP;
        #pragma unroll
        for (int kk = 0; kk < 16; kk += 8) {
            wmma::fragment<wmma::matrix_a, 16, 16, 8, wmma::precision::tf32, wmma::row_major> a[2];
            wmma::fragment<wmma::matrix_b, 16, 16, 8, wmma::precision::tf32, wmma::col_major> bf[3];
            #pragma unroll
            for (int i = 0; i < 2; ++i) {
                wmma::load_matrix_sync(a[i], &As[(wm * 32 + i * 16) * SKP + kk], SKP);
                #pragma unroll
                for (int e = 0; e < a[i].num_elements; ++e)
                    a[i].x[e] = wmma::__float_to_tf32(a[i].x[e]);
            }
            #pragma unroll
            for (int j = 0; j < 3; ++j) {
                wmma::load_matrix_sync(bf[j], &Bs[(wn * 48 + j * 16) * SKP + kk], SKP);
                #pragma unroll
                for (int e = 0; e < bf[j].num_elements; ++e)
                    bf[j].x[e] = wmma::__float_to_tf32(bf[j].x[e]);
            }
            #pragma unroll
            for (int i = 0; i < 2; ++i)
                #pragma unroll
                for (int j = 0; j < 3; ++j)
                    wmma::mma_sync(acc[i][j], a[i], bf[j], acc[i][j]);
        }
        __syncthreads();
    }

    // epilogue (reuse sm as per-warp patch: 6 warps x 16 x SKP)
    float* patch = sm + warp * 16 * SKP;
    float* wrow = g_w + (size_t)b * OO * CP;
    #pragma unroll
    for (int i = 0; i < 2; ++i) {
        #pragma unroll
        for (int j = 0; j < 3; ++j) {
            int r0 = m0 + wm * 32 + i * 16;
            int c0 = n0 + wn * 48 + j * 16;
            if (r0 + 16 <= OO) {
                wmma::store_matrix_sync(&wrow[(size_t)r0 * CP + c0], acc[i][j],
                                        CP, wmma::mem_row_major);
            } else {
                wmma::store_matrix_sync(patch, acc[i][j], SKP, wmma::mem_row_major);
                __syncwarp();
                for (int e = lane; e < 256; e += 32) {
                    int r = e >> 4, cc2 = e & 15;
                    if (r0 + r < OO)
                        wrow[(size_t)(r0 + r) * CP + c0 + cc2] = patch[r * SKP + cc2];
                }
                __syncwarp();
            }
        }
    }
}

// ---------------------------------------------------------------------------
// Stage 3: softmax over c (273 of 288) per (b,o) row; zero the pad.
// ---------------------------------------------------------------------------
__global__ __launch_bounds__(128) void softmax_kernel() {
    int row = blockIdx.x;
    float* s = g_w + (size_t)row * CP;
    int tid = threadIdx.x;
    __shared__ float sred[4];

    float m = -1e30f;
    for (int c = tid; c < CC; c += 128) m = fmaxf(m, s[c]);
    #pragma unroll
    for (int o = 16; o > 0; o >>= 1) m = fmaxf(m, __shfl_xor_sync(0xFFFFFFFFu, m, o));
    if ((tid & 31) == 0) sred[tid >> 5] = m;
    __syncthreads();
    m = fmaxf(fmaxf(sred[0], sred[1]), fmaxf(sred[2], sred[3]));
    __syncthreads();

    float sum = 0.f;
    for (int c = tid; c < CC; c += 128) {
        float e = __expf(s[c] - m);
        s[c] = e;
        sum += e;
    }
    #pragma unroll
    for (int o = 16; o > 0; o >>= 1) sum += __shfl_xor_sync(0xFFFFFFFFu, sum, o);
    if ((tid & 31) == 0) sred[tid >> 5] = sum;
    __syncthreads();
    sum = sred[0] + sred[1] + sred[2] + sred[3];

    float inv = 1.0f / sum;
    for (int c = tid; c < CP; c += 128) {
        if (c < CC) s[c] *= inv;
        else        s[c] = 0.f;
    }
}

// ---------------------------------------------------------------------------
// Stage 4: out[b,o,t] = sum_c w[b,o,c] * brain[b,c,t]  (tf32, 2-stage cp.async)
// Block 96x256, BK=16, 12 warps (3x4), warp tile 32x64 (2x4 frags).
// ---------------------------------------------------------------------------
#define OBN  256
#define OBNP 260        // B smem pitch (1040B = 65x16B)
#define OKP  20         // A smem pitch

__global__ __launch_bounds__(384) void out_kernel(const float* __restrict__ brain,
                                                  float* __restrict__ out) {
    // As[2][96][20] = 3840 floats | Bs[2][16][260] = 8320 floats -> 48.6KB
    __shared__ float sm[2 * 96 * OKP + 2 * 16 * OBNP];
    float* Asb = sm;                       // + s*1920
    float* Bsb = sm + 2 * 96 * OKP;        // + s*4160

    int b  = blockIdx.z;
    int m0 = blockIdx.y * 96;
    int n0 = blockIdx.x * OBN;
    int tid = threadIdx.x, warp = tid >> 5, lane = tid & 31;
    int wm = warp >> 2;                    // 0..2
    int wn = warp & 3;                     // 0..3

    const float* __restrict__ wB = g_w   + (size_t)b * OO * CP;
    const float* __restrict__ xB = brain + (size_t)b * CC * TT;

    wmma::fragment<wmma::accumulator, 16, 16, 8, float> acc[2][4];
    #pragma unroll
    for (int i = 0; i < 2; ++i)
        #pragma unroll
        for (int j = 0; j < 4; ++j) wmma::fill_fragment(acc[i][j], 0.0f);

    const int NK = CP / 16;   // 18

    auto load_tile = [&](int s, int k0) {
        float* As = Asb + s * 96 * OKP;
        float* Bs = Bsb + s * 16 * OBNP;
        {   // A: 96x16 = 384 float4 slots, 1 per thread
            int row = tid >> 2, q = tid & 3;
            int o = m0 + row;
            cp_async16(&As[row * OKP + q * 4], &wB[(size_t)o * CP + k0 + q * 4], o < OO);
        }
        #pragma unroll
        for (int l = 0; l < 3; ++l) {       // B: 16x256 = 1024 float4 slots
            int idx = tid + l * 384;
            if (idx < 1024) {
                int row = idx >> 6, col = (idx & 63) << 2;
                int c = k0 + row, t = n0 + col;
                cp_async16(&Bs[row * OBNP + col], &xB[(size_t)c * TT + t],
                           (c < CC) && (t < TT));
            }
        }
        cp_commit();
    };

    load_tile(0, 0);
    for (int ks = 0; ks < NK; ++ks) {
        if (ks + 1 < NK) { load_tile((ks + 1) & 1, (ks + 1) * 16); cp_wait<1>(); }
        else             { cp_wait<0>(); }
        __syncthreads();

        const float* As = Asb + (ks & 1) * 96 * OKP;
        const float* Bs = Bsb + (ks & 1) * 16 * OBNP;
        #pragma unroll
        for (int kk = 0; kk < 16; kk += 8) {
            wmma::fragment<wmma::matrix_a, 16, 16, 8, wmma::precision::tf32, wmma::row_major> a[2];
            wmma::fragment<wmma::matrix_b, 16, 16, 8, wmma::precision::tf32, wmma::row_major> bf[4];
            #pragma unroll
            for (int i = 0; i < 2; ++i) {
                wmma::load_matrix_sync(a[i], &As[(wm * 32 + i * 16) * OKP + kk], OKP);
                #pragma unroll
                for (int e = 0; e < a[i].num_elements; ++e)
                    a[i].x[e] = wmma::__float_to_tf32(a[i].x[e]);
            }
            #pragma unroll
            for (int j = 0; j < 4; ++j) {
                wmma::load_matrix_sync(bf[j], &Bs[kk * OBNP + wn * 64 + j * 16], OBNP);
                #pragma unroll
                for (int e = 0; e < bf[j].num_elements; ++e)
                    bf[j].x[e] = wmma::__float_to_tf32(bf[j].x[e]);
            }
            #pragma unroll
            for (int i = 0; i < 2; ++i)
                #pragma unroll
                for (int j = 0; j < 4; ++j)
                    wmma::mma_sync(acc[i][j], a[i], bf[j], acc[i][j]);
        }
        __syncthreads();
    }

    // epilogue (reuse sm as per-warp patch: 12 warps x 16 x OKP = 3840 floats)
    float* patch = sm + warp * 16 * OKP;
    #pragma unroll
    for (int i = 0; i < 2; ++i) {
        #pragma unroll
        for (int j = 0; j < 4; ++j) {
            int r0 = m0 + wm * 32 + i * 16;
            int t0 = n0 + wn * 64 + j * 16;
            if (r0 + 16 <= OO && t0 + 16 <= TT) {
                wmma::store_matrix_sync(&out[((size_t)b * OO + r0) * TT + t0],
                                        acc[i][j], TT, wmma::mem_row_major);
            } else {
                wmma::store_matrix_sync(patch, acc[i][j], OKP, wmma::mem_row_major);
                __syncwarp();
                for (int e = lane; e < 256; e += 32) {
                    int r = e >> 4, cc2 = e & 15;
                    int o = r0 + r, t = t0 + cc2;
                    if (o < OO && t < TT)
                        out[((size_t)b * OO + o) * TT + t] = patch[r * OKP + cc2];
                }
                __syncwarp();
            }
        }
    }
}

// ---------------------------------------------------------------------------
// Launch
// ---------------------------------------------------------------------------
extern "C" void kernel_launch(void* const* d_in, const int* in_sizes, int n_in,
                              void* d_out, int out_size) {
    const float* brain  = (const float*)d_in[0];   // [32, 273, 3000]
    const float* layout = (const float*)d_in[1];   // [32, 273, 2]
    const float* heads  = (const float*)d_in[2];   // [270, 2048]
    float* out = (float*)d_out;                    // [32, 270, 3000]

    emb_kernel<<<BB * CC, 256>>>(layout);

    dim3 gs((CP + 95) / 96, (OO + 95) / 96, BB);          // (3, 3, 32)
    scores_kernel<<<gs, 192>>>(heads);

    softmax_kernel<<<BB * OO, 128>>>();

    dim3 go((TT + OBN - 1) / OBN, (OO + 95) / 96, BB);    // (12, 3, 32)
    out_kernel<<<go, 384>>>(brain, out);
}